// round 15
// baseline (speedup 1.0000x reference)
#include <cuda_runtime.h>
#include <cuda_fp16.h>
#include <math.h>
#include <cstdint>

#define TT 8192
#define HH 2048
#define NCHUNK 128
#define CLEN 64

// GEMM tiling (R8 config: best measured; smem-crossbar-bound floor)
#define BM 128
#define BN 128
#define BKE 64
#define LDA 72
#define TILE_ELEMS (128 * LDA)
#define STAGE_BYTES (2 * TILE_ELEMS * 2)
#define NSTAGE 3
#define GSMEM (NSTAGE * STAGE_BYTES)       // 110592 -> 2 CTAs/SM
#define KITER (HH / BKE)                   // 32

// ---------------- scratch (device globals; allocation-free) ----------------
__device__ __half g_kh[TT * HH];
__device__ __half g_vh[TT * HH];
__device__ __half g_rh[TT * HH];
__device__ __half g_ax[3][TT * HH];
__device__ __half g_wt[4][HH * HH];
__device__ __half g_rw[TT * HH];
__device__ float g_Sa[NCHUNK * HH];
__device__ float g_Sb[NCHUNK * HH];
__device__ float g_Sm[NCHUNK * HH];

// ---------------- PTX helpers ----------------
__device__ __forceinline__ uint32_t smem_u32(const void* p) {
    uint32_t a;
    asm("{ .reg .u64 t; cvta.to.shared.u64 t, %1; cvt.u32.u64 %0, t; }" : "=r"(a) : "l"(p));
    return a;
}

#define CP_ASYNC16(dst, src) \
    asm volatile("cp.async.cg.shared.global [%0], [%1], 16;" :: "r"(dst), "l"(src))
#define CP_COMMIT() asm volatile("cp.async.commit_group;" ::: "memory")
#define CP_WAIT1() asm volatile("cp.async.wait_group 1;" ::: "memory")
#define CP_WAIT0() asm volatile("cp.async.wait_group 0;" ::: "memory")

__device__ __forceinline__ void ldmx4(uint32_t* r, uint32_t addr) {
    asm volatile("ldmatrix.sync.aligned.m8n8.x4.shared.b16 {%0,%1,%2,%3}, [%4];"
                 : "=r"(r[0]), "=r"(r[1]), "=r"(r[2]), "=r"(r[3]) : "r"(addr));
}

__device__ __forceinline__ void mma16816(float* d, const uint32_t* a, uint32_t b0, uint32_t b1) {
    asm volatile("mma.sync.aligned.m16n8k16.row.col.f32.f16.f16.f32 "
                 "{%0,%1,%2,%3}, {%4,%5,%6,%7}, {%8,%9}, {%0,%1,%2,%3};"
                 : "+f"(d[0]), "+f"(d[1]), "+f"(d[2]), "+f"(d[3])
                 : "r"(a[0]), "r"(a[1]), "r"(a[2]), "r"(a[3]), "r"(b0), "r"(b1));
}

// ---------------- shared GEMM mainloop ----------------
struct GemmCtx {
    uint32_t sbase;
    int tid, wid, lid, wm, wn, r0c, c16, lrow, khalf;
};

__device__ __forceinline__ void gemm_main(
    const __half* __restrict__ A, const __half* __restrict__ B,
    int row0, int col0, const GemmCtx& cx, float acc[2][8][4])
{
#pragma unroll
    for (int mi = 0; mi < 2; ++mi)
#pragma unroll
        for (int ni = 0; ni < 8; ++ni)
#pragma unroll
            for (int j = 0; j < 4; ++j) acc[mi][ni][j] = 0.f;

    auto load_stage = [&](int buf, int it) {
        const int kt = it * BKE;
        const uint32_t sA = cx.sbase + buf * STAGE_BYTES;
        const uint32_t sB = sA + TILE_ELEMS * 2;
#pragma unroll
        for (int i = 0; i < 4; ++i) {
            const int r = cx.r0c + i * 32;
            const uint32_t so = (r * LDA + cx.c16 * 8) * 2;
            CP_ASYNC16(sA + so, A + (size_t)(row0 + r) * HH + kt + cx.c16 * 8);
            CP_ASYNC16(sB + so, B + (size_t)(col0 + r) * HH + kt + cx.c16 * 8);
        }
        CP_COMMIT();
    };

    load_stage(0, 0);
    load_stage(1, 1);

    int buf = 0, nb = 2;
    for (int it = 0; it < KITER; ++it) {
        CP_WAIT1();
        __syncthreads();
        if (it + 2 < KITER) load_stage(nb, it + 2);

        const uint32_t sA = cx.sbase + buf * STAGE_BYTES;
        const uint32_t sB = sA + TILE_ELEMS * 2;
#pragma unroll
        for (int k16 = 0; k16 < 4; ++k16) {
            uint32_t a[2][4], b[4][4];
#pragma unroll
            for (int mi = 0; mi < 2; ++mi)
                ldmx4(a[mi], sA + ((cx.wm + 16 * mi + cx.lrow) * LDA + k16 * 16 + cx.khalf) * 2);
#pragma unroll
            for (int nt = 0; nt < 4; ++nt)
                ldmx4(b[nt], sB + ((cx.wn + 16 * nt + cx.lrow) * LDA + k16 * 16 + cx.khalf) * 2);
#pragma unroll
            for (int mi = 0; mi < 2; ++mi)
#pragma unroll
                for (int nt = 0; nt < 4; ++nt) {
                    mma16816(acc[mi][2 * nt + 0], a[mi], b[nt][0], b[nt][2]);
                    mma16816(acc[mi][2 * nt + 1], a[mi], b[nt][1], b[nt][3]);
                }
        }
        buf = (buf + 1 == NSTAGE) ? 0 : buf + 1;
        nb = (nb + 1 == NSTAGE) ? 0 : nb + 1;
    }
    CP_WAIT0();
}

__device__ __forceinline__ GemmCtx make_ctx(const void* smem) {
    GemmCtx cx;
    cx.sbase = smem_u32(smem);
    cx.tid = threadIdx.x;
    cx.wid = cx.tid >> 5; cx.lid = cx.tid & 31;
    cx.wm = (cx.wid >> 1) * 32;
    cx.wn = (cx.wid & 1) * 64;
    cx.r0c = cx.tid >> 3;
    cx.c16 = cx.tid & 7;
    cx.lrow = cx.lid & 15;
    cx.khalf = (cx.lid >> 4) * 8;
    return cx;
}

// ================= fused k/v/r GEMM =================
__global__ void __launch_bounds__(256, 2)
mmagemm_kvr()
{
    extern __shared__ __half sm[];
    const GemmCtx cx = make_ctx(sm);
    const int z = blockIdx.z;
    const int row0 = blockIdx.y * BM;
    const int col0 = blockIdx.x * BN;
    const __half* A = &g_ax[z][0];
    const __half* B = &g_wt[z][0];
    __half* out = (z == 0) ? g_kh : (z == 1) ? g_vh : g_rh;

    float acc[2][8][4];
    gemm_main(A, B, row0, col0, cx, acc);

    const int erow = cx.wm + (cx.lid >> 2);
    const int ecol = cx.wn + (cx.lid & 3) * 2;
#pragma unroll
    for (int mi = 0; mi < 2; ++mi)
#pragma unroll
        for (int ni = 0; ni < 8; ++ni)
#pragma unroll
            for (int h = 0; h < 2; ++h) {
                const int r = row0 + erow + mi * 16 + h * 8;
                const int c = col0 + ecol + ni * 8;
                __half2 v = __floats2half2_rn(acc[mi][ni][h * 2 + 0], acc[mi][ni][h * 2 + 1]);
                *reinterpret_cast<__half2*>(out + (size_t)r * HH + c) = v;
            }
}

// ================= final GEMM: out = hidden + rw @ Wo^T =================
__global__ void __launch_bounds__(256, 2)
mmagemm_out(const float* __restrict__ addv, float* __restrict__ out)
{
    extern __shared__ __half sm[];
    const GemmCtx cx = make_ctx(sm);
    const int row0 = blockIdx.y * BM;
    const int col0 = blockIdx.x * BN;

    float acc[2][8][4];
    gemm_main(&g_rw[0], &g_wt[3][0], row0, col0, cx, acc);

    const int erow = cx.wm + (cx.lid >> 2);
    const int ecol = cx.wn + (cx.lid & 3) * 2;
#pragma unroll
    for (int mi = 0; mi < 2; ++mi)
#pragma unroll
        for (int ni = 0; ni < 8; ++ni)
#pragma unroll
            for (int h = 0; h < 2; ++h) {
                const int r = row0 + erow + mi * 16 + h * 8;
                const int c = col0 + ecol + ni * 8;
                const size_t o = (size_t)r * HH + c;
                float2 hv = *reinterpret_cast<const float2*>(addv + o);
                float2 v;
                v.x = acc[mi][ni][h * 2 + 0] + hv.x;
                v.y = acc[mi][ni][h * 2 + 1] + hv.y;
                *reinterpret_cast<float2*>(out + o) = v;
            }
}

// ================= split / transpose prep =================
__global__ void __launch_bounds__(256)
split_acts(const float* __restrict__ hidden, const float* __restrict__ sx,
           const float* __restrict__ tmk, const float* __restrict__ tmv,
           const float* __restrict__ tmr)
{
    const int idx = blockIdx.x * 256 + threadIdx.x;  // float4 index
    const int h4 = idx & (HH / 4 - 1);
    float4 hv = reinterpret_cast<const float4*>(hidden)[idx];
    float4 pv = (idx >= HH / 4) ? reinterpret_cast<const float4*>(hidden)[idx - HH / 4]
                                : reinterpret_cast<const float4*>(sx)[h4];
    const float* tms[3] = {tmk, tmv, tmr};
#pragma unroll
    for (int p = 0; p < 3; ++p) {
        float4 mv = reinterpret_cast<const float4*>(tms[p])[h4];
        union { __half b[4]; uint2 u; } Hh;
        Hh.b[0] = __float2half_rn(fmaf(hv.x - pv.x, mv.x, pv.x));
        Hh.b[1] = __float2half_rn(fmaf(hv.y - pv.y, mv.y, pv.y));
        Hh.b[2] = __float2half_rn(fmaf(hv.z - pv.z, mv.z, pv.z));
        Hh.b[3] = __float2half_rn(fmaf(hv.w - pv.w, mv.w, pv.w));
        *reinterpret_cast<uint2*>(&g_ax[p][(size_t)idx * 4]) = Hh.u;
    }
}

// W[K,N] -> W^T[N,K] fp16
__global__ void __launch_bounds__(256)
wtrans4(const float* __restrict__ W0, const float* __restrict__ W1,
        const float* __restrict__ W2, const float* __restrict__ W3)
{
    __shared__ float ts[32][33];
    const int z = blockIdx.z;
    const float* W = (z == 0) ? W0 : (z == 1) ? W1 : (z == 2) ? W2 : W3;
    __half* T = &g_wt[z][0];
    const int n0 = blockIdx.x * 32, k0 = blockIdx.y * 32;
    const int tx = threadIdx.x, ty = threadIdx.y;  // 32 x 8
#pragma unroll
    for (int i = 0; i < 4; ++i)
        ts[ty + i * 8][tx] = W[(size_t)(k0 + ty + i * 8) * HH + n0 + tx];
    __syncthreads();
#pragma unroll
    for (int i = 0; i < 4; ++i) {
        const size_t o = (size_t)(n0 + ty + i * 8) * HH + k0 + tx;
        T[o] = __float2half_rn(ts[tx][ty + i * 8]);
    }
}

// ================= WKV chunked scan =================
// Phase A: per-chunk summaries. 2 channels/thread, __half2 loads, unrolled for MLP.
__global__ void scan_phaseA(const float* __restrict__ td)
{
    int h2 = blockIdx.x * blockDim.x + threadIdx.x;
    int h = h2 * 2;
    int c = blockIdx.y;
    float w0 = -expf(td[h]), w1 = -expf(td[h + 1]);
    float a0 = 0.f, b0 = 0.f, p0 = -1e30f;
    float a1 = 0.f, b1 = 0.f, p1 = -1e30f;
    int t0 = c * CLEN;
#pragma unroll 4
    for (int t = t0; t < t0 + CLEN; ++t) {
        size_t idx = (size_t)t * HH + h;
        float2 kk = __half22float2(*reinterpret_cast<const __half2*>(&g_kh[idx]));
        float2 vv = __half22float2(*reinterpret_cast<const __half2*>(&g_vh[idx]));
        {
            float ww = w0 + p0, d = ww - kk.x;
            float e = __expf(-fabsf(d));
            float e1 = (d >= 0.f) ? 1.f : e, e2 = (d >= 0.f) ? e : 1.f;
            a0 = e1 * a0 + e2 * vv.x; b0 = e1 * b0 + e2; p0 = fmaxf(ww, kk.x);
        }
        {
            float ww = w1 + p1, d = ww - kk.y;
            float e = __expf(-fabsf(d));
            float e1 = (d >= 0.f) ? 1.f : e, e2 = (d >= 0.f) ? e : 1.f;
            a1 = e1 * a1 + e2 * vv.y; b1 = e1 * b1 + e2; p1 = fmaxf(ww, kk.y);
        }
    }
    *reinterpret_cast<float2*>(&g_Sa[c * HH + h]) = make_float2(a0, a1);
    *reinterpret_cast<float2*>(&g_Sb[c * HH + h]) = make_float2(b0, b1);
    *reinterpret_cast<float2*>(&g_Sm[c * HH + h]) = make_float2(p0, p1);
}

// Phase C (with inlined prefix combine replacing old phaseB):
// each block computes its own chunk-prefix from the summaries, then replays its chunk.
__global__ void scan_phaseC(const float* __restrict__ td, const float* __restrict__ tf,
                            const float* __restrict__ aa0, const float* __restrict__ bb0,
                            const float* __restrict__ pp0, const float* __restrict__ hidden,
                            float* __restrict__ out)
{
    int h2 = blockIdx.x * blockDim.x + threadIdx.x;
    int h = h2 * 2;
    int c = blockIdx.y;
    float w0 = -expf(td[h]), w1 = -expf(td[h + 1]);
    float u0 = tf[h], u1 = tf[h + 1];
    float wL0 = w0 * (float)CLEN, wL1 = w1 * (float)CLEN;

    // prefix combine over chunks 0..c-1 (prefetched sequential scan)
    float a0 = aa0[h], b0 = bb0[h], p0 = pp0[h];
    float a1 = aa0[h + 1], b1 = bb0[h + 1], p1 = pp0[h + 1];
    if (c > 0) {
        float2 sa = *reinterpret_cast<const float2*>(&g_Sa[h]);
        float2 sb = *reinterpret_cast<const float2*>(&g_Sb[h]);
        float2 sm = *reinterpret_cast<const float2*>(&g_Sm[h]);
        for (int cc = 0; cc < c; ++cc) {
            float2 nsa, nsb, nsm;
            if (cc + 1 < c) {
                nsa = *reinterpret_cast<const float2*>(&g_Sa[(cc + 1) * HH + h]);
                nsb = *reinterpret_cast<const float2*>(&g_Sb[(cc + 1) * HH + h]);
                nsm = *reinterpret_cast<const float2*>(&g_Sm[(cc + 1) * HH + h]);
            }
            {
                float pd = p0 + wL0, d = pd - sm.x;
                float e = __expf(-fabsf(d));
                float e1 = (d >= 0.f) ? 1.f : e, e2 = (d >= 0.f) ? e : 1.f;
                a0 = e1 * a0 + e2 * sa.x; b0 = e1 * b0 + e2 * sb.x; p0 = fmaxf(pd, sm.x);
            }
            {
                float pd = p1 + wL1, d = pd - sm.y;
                float e = __expf(-fabsf(d));
                float e1 = (d >= 0.f) ? 1.f : e, e2 = (d >= 0.f) ? e : 1.f;
                a1 = e1 * a1 + e2 * sa.y; b1 = e1 * b1 + e2 * sb.y; p1 = fmaxf(pd, sm.y);
            }
            sa = nsa; sb = nsb; sm = nsm;
        }
    }

    // replay this chunk, emitting sigmoid(r)*wkv
    int t0 = c * CLEN;
#pragma unroll 4
    for (int t = t0; t < t0 + CLEN; ++t) {
        size_t idx = (size_t)t * HH + h;
        float2 kk = __half22float2(*reinterpret_cast<const __half2*>(&g_kh[idx]));
        float2 vv = __half22float2(*reinterpret_cast<const __half2*>(&g_vh[idx]));
        float2 rr = __half22float2(*reinterpret_cast<const __half2*>(&g_rh[idx]));
        float rw0, rw1;
        {
            float ww = u0 + kk.x, d1 = p0 - ww;
            float e = __expf(-fabsf(d1));
            float e1 = (d1 >= 0.f) ? 1.f : e, e2 = (d1 >= 0.f) ? e : 1.f;
            float num = e1 * a0 + e2 * vv.x;
            float den = e1 * b0 + e2;
            float sr = 1.f + __expf(-rr.x);
            rw0 = num * __frcp_rn(den * sr);
            float ww2 = w0 + p0, d2 = ww2 - kk.x;
            float f = __expf(-fabsf(d2));
            float f1 = (d2 >= 0.f) ? 1.f : f, f2 = (d2 >= 0.f) ? f : 1.f;
            a0 = f1 * a0 + f2 * vv.x; b0 = f1 * b0 + f2; p0 = fmaxf(ww2, kk.x);
        }
        {
            float ww = u1 + kk.y, d1 = p1 - ww;
            float e = __expf(-fabsf(d1));
            float e1 = (d1 >= 0.f) ? 1.f : e, e2 = (d1 >= 0.f) ? e : 1.f;
            float num = e1 * a1 + e2 * vv.y;
            float den = e1 * b1 + e2;
            float sr = 1.f + __expf(-rr.y);
            rw1 = num * __frcp_rn(den * sr);
            float ww2 = w1 + p1, d2 = ww2 - kk.y;
            float f = __expf(-fabsf(d2));
            float f1 = (d2 >= 0.f) ? 1.f : f, f2 = (d2 >= 0.f) ? f : 1.f;
            a1 = f1 * a1 + f2 * vv.y; b1 = f1 * b1 + f2; p1 = fmaxf(ww2, kk.y);
        }
        *reinterpret_cast<__half2*>(&g_rw[idx]) = __floats2half2_rn(rw0, rw1);
    }

    // last chunk's block also emits the final state + last hidden row
    if (c == NCHUNK - 1) {
        out[TT * HH + h]     = hidden[(TT - 1) * HH + h];
        out[TT * HH + h + 1] = hidden[(TT - 1) * HH + h + 1];
        out[TT * HH + HH + h]     = a0;
        out[TT * HH + HH + h + 1] = a1;
        out[TT * HH + 2 * HH + h]     = b0;
        out[TT * HH + 2 * HH + h + 1] = b1;
        out[TT * HH + 3 * HH + h]     = p0;
        out[TT * HH + 3 * HH + h + 1] = p1;
    }
}

extern "C" void kernel_launch(void* const* d_in, const int* in_sizes, int n_in,
                              void* d_out, int out_size)
{
    const float* hidden = (const float*)d_in[0];
    const float* sx     = (const float*)d_in[1];
    const float* aa     = (const float*)d_in[2];
    const float* bb     = (const float*)d_in[3];
    const float* pp     = (const float*)d_in[4];
    const float* td     = (const float*)d_in[5];
    const float* tf     = (const float*)d_in[6];
    const float* tmk    = (const float*)d_in[7];
    const float* tmv    = (const float*)d_in[8];
    const float* tmr    = (const float*)d_in[9];
    const float* Wk     = (const float*)d_in[10];
    const float* Wv     = (const float*)d_in[11];
    const float* Wr     = (const float*)d_in[12];
    const float* Wo     = (const float*)d_in[13];
    float* out = (float*)d_out;

    cudaFuncSetAttribute(mmagemm_kvr, cudaFuncAttributeMaxDynamicSharedMemorySize, GSMEM);
    cudaFuncSetAttribute(mmagemm_out, cudaFuncAttributeMaxDynamicSharedMemorySize, GSMEM);

    dim3 wgrid(HH / 32, HH / 32, 4), wblk(32, 8);
    wtrans4<<<wgrid, wblk>>>(Wk, Wv, Wr, Wo);
    split_acts<<<(TT * HH / 4) / 256, 256>>>(hidden, sx, tmk, tmv, tmr);

    dim3 gkvr(HH / BN, TT / BM, 3);
    mmagemm_kvr<<<gkvr, 256, GSMEM>>>();

    dim3 sgrid(HH / 2 / 256, NCHUNK);
    scan_phaseA<<<sgrid, 256>>>(td);
    scan_phaseC<<<sgrid, 256>>>(td, tf, aa, bb, pp, hidden, out);

    dim3 gg(HH / BN, TT / BM);
    mmagemm_out<<<gg, 256, GSMEM>>>(hidden, out);
}

// round 16
// speedup vs baseline: 1.0206x; 1.0206x over previous
#include <cuda_runtime.h>
#include <cuda_fp16.h>
#include <math.h>
#include <cstdint>

#define TT 8192
#define HH 2048
#define NCHUNK 128
#define CLEN 64

// GEMM tiling (R8 config: best measured; smem-crossbar-bound floor)
#define BM 128
#define BN 128
#define BKE 64
#define LDA 72
#define TILE_ELEMS (128 * LDA)
#define STAGE_BYTES (2 * TILE_ELEMS * 2)
#define NSTAGE 3
#define GSMEM (NSTAGE * STAGE_BYTES)       // 110592 -> 2 CTAs/SM
#define KITER (HH / BKE)                   // 32

// ---------------- scratch (device globals; allocation-free) ----------------
__device__ __half g_kh[TT * HH];
__device__ __half g_vh[TT * HH];
__device__ __half g_rh[TT * HH];
__device__ __half g_ax[3][TT * HH];
__device__ __half g_wt[4][HH * HH];
__device__ __half g_rw[TT * HH];
__device__ float g_Sa[NCHUNK * HH];
__device__ float g_Sb[NCHUNK * HH];
__device__ float g_Sm[NCHUNK * HH];
__device__ float g_Pa[NCHUNK * HH];
__device__ float g_Pb[NCHUNK * HH];
__device__ float g_Pp[NCHUNK * HH];

// ---------------- PTX helpers ----------------
__device__ __forceinline__ uint32_t smem_u32(const void* p) {
    uint32_t a;
    asm("{ .reg .u64 t; cvta.to.shared.u64 t, %1; cvt.u32.u64 %0, t; }" : "=r"(a) : "l"(p));
    return a;
}

#define CP_ASYNC16(dst, src) \
    asm volatile("cp.async.cg.shared.global [%0], [%1], 16;" :: "r"(dst), "l"(src))
#define CP_COMMIT() asm volatile("cp.async.commit_group;" ::: "memory")
#define CP_WAIT1() asm volatile("cp.async.wait_group 1;" ::: "memory")
#define CP_WAIT0() asm volatile("cp.async.wait_group 0;" ::: "memory")

__device__ __forceinline__ void ldmx4(uint32_t* r, uint32_t addr) {
    asm volatile("ldmatrix.sync.aligned.m8n8.x4.shared.b16 {%0,%1,%2,%3}, [%4];"
                 : "=r"(r[0]), "=r"(r[1]), "=r"(r[2]), "=r"(r[3]) : "r"(addr));
}

__device__ __forceinline__ void mma16816(float* d, const uint32_t* a, uint32_t b0, uint32_t b1) {
    asm volatile("mma.sync.aligned.m16n8k16.row.col.f32.f16.f16.f32 "
                 "{%0,%1,%2,%3}, {%4,%5,%6,%7}, {%8,%9}, {%0,%1,%2,%3};"
                 : "+f"(d[0]), "+f"(d[1]), "+f"(d[2]), "+f"(d[3])
                 : "r"(a[0]), "r"(a[1]), "r"(a[2]), "r"(a[3]), "r"(b0), "r"(b1));
}

// ---------------- shared GEMM mainloop ----------------
struct GemmCtx {
    uint32_t sbase;
    int tid, wid, lid, wm, wn, r0c, c16, lrow, khalf;
};

__device__ __forceinline__ void gemm_main(
    const __half* __restrict__ A, const __half* __restrict__ B,
    int row0, int col0, const GemmCtx& cx, float acc[2][8][4])
{
#pragma unroll
    for (int mi = 0; mi < 2; ++mi)
#pragma unroll
        for (int ni = 0; ni < 8; ++ni)
#pragma unroll
            for (int j = 0; j < 4; ++j) acc[mi][ni][j] = 0.f;

    auto load_stage = [&](int buf, int it) {
        const int kt = it * BKE;
        const uint32_t sA = cx.sbase + buf * STAGE_BYTES;
        const uint32_t sB = sA + TILE_ELEMS * 2;
#pragma unroll
        for (int i = 0; i < 4; ++i) {
            const int r = cx.r0c + i * 32;
            const uint32_t so = (r * LDA + cx.c16 * 8) * 2;
            CP_ASYNC16(sA + so, A + (size_t)(row0 + r) * HH + kt + cx.c16 * 8);
            CP_ASYNC16(sB + so, B + (size_t)(col0 + r) * HH + kt + cx.c16 * 8);
        }
        CP_COMMIT();
    };

    load_stage(0, 0);
    load_stage(1, 1);

    int buf = 0, nb = 2;
    for (int it = 0; it < KITER; ++it) {
        CP_WAIT1();
        __syncthreads();
        if (it + 2 < KITER) load_stage(nb, it + 2);

        const uint32_t sA = cx.sbase + buf * STAGE_BYTES;
        const uint32_t sB = sA + TILE_ELEMS * 2;
#pragma unroll
        for (int k16 = 0; k16 < 4; ++k16) {
            uint32_t a[2][4], b[4][4];
#pragma unroll
            for (int mi = 0; mi < 2; ++mi)
                ldmx4(a[mi], sA + ((cx.wm + 16 * mi + cx.lrow) * LDA + k16 * 16 + cx.khalf) * 2);
#pragma unroll
            for (int nt = 0; nt < 4; ++nt)
                ldmx4(b[nt], sB + ((cx.wn + 16 * nt + cx.lrow) * LDA + k16 * 16 + cx.khalf) * 2);
#pragma unroll
            for (int mi = 0; mi < 2; ++mi)
#pragma unroll
                for (int nt = 0; nt < 4; ++nt) {
                    mma16816(acc[mi][2 * nt + 0], a[mi], b[nt][0], b[nt][2]);
                    mma16816(acc[mi][2 * nt + 1], a[mi], b[nt][1], b[nt][3]);
                }
        }
        buf = (buf + 1 == NSTAGE) ? 0 : buf + 1;
        nb = (nb + 1 == NSTAGE) ? 0 : nb + 1;
    }
    CP_WAIT0();
}

__device__ __forceinline__ GemmCtx make_ctx(const void* smem) {
    GemmCtx cx;
    cx.sbase = smem_u32(smem);
    cx.tid = threadIdx.x;
    cx.wid = cx.tid >> 5; cx.lid = cx.tid & 31;
    cx.wm = (cx.wid >> 1) * 32;
    cx.wn = (cx.wid & 1) * 64;
    cx.r0c = cx.tid >> 3;
    cx.c16 = cx.tid & 7;
    cx.lrow = cx.lid & 15;
    cx.khalf = (cx.lid >> 4) * 8;
    return cx;
}

// ================= k/v/r GEMM: z = zbase + blockIdx.z =================
__global__ void __launch_bounds__(256, 2)
mmagemm_kvr(int zbase)
{
    extern __shared__ __half sm[];
    const GemmCtx cx = make_ctx(sm);
    const int z = zbase + blockIdx.z;
    const int row0 = blockIdx.y * BM;
    const int col0 = blockIdx.x * BN;
    const __half* A = &g_ax[z][0];
    const __half* B = &g_wt[z][0];
    __half* out = (z == 0) ? g_kh : (z == 1) ? g_vh : g_rh;

    float acc[2][8][4];
    gemm_main(A, B, row0, col0, cx, acc);

    const int erow = cx.wm + (cx.lid >> 2);
    const int ecol = cx.wn + (cx.lid & 3) * 2;
#pragma unroll
    for (int mi = 0; mi < 2; ++mi)
#pragma unroll
        for (int ni = 0; ni < 8; ++ni)
#pragma unroll
            for (int h = 0; h < 2; ++h) {
                const int r = row0 + erow + mi * 16 + h * 8;
                const int c = col0 + ecol + ni * 8;
                __half2 v = __floats2half2_rn(acc[mi][ni][h * 2 + 0], acc[mi][ni][h * 2 + 1]);
                *reinterpret_cast<__half2*>(out + (size_t)r * HH + c) = v;
            }
}

// ================= final GEMM: out = hidden + rw @ Wo^T =================
__global__ void __launch_bounds__(256, 2)
mmagemm_out(const float* __restrict__ addv, float* __restrict__ out)
{
    extern __shared__ __half sm[];
    const GemmCtx cx = make_ctx(sm);
    const int row0 = blockIdx.y * BM;
    const int col0 = blockIdx.x * BN;

    float acc[2][8][4];
    gemm_main(&g_rw[0], &g_wt[3][0], row0, col0, cx, acc);

    const int erow = cx.wm + (cx.lid >> 2);
    const int ecol = cx.wn + (cx.lid & 3) * 2;
#pragma unroll
    for (int mi = 0; mi < 2; ++mi)
#pragma unroll
        for (int ni = 0; ni < 8; ++ni)
#pragma unroll
            for (int h = 0; h < 2; ++h) {
                const int r = row0 + erow + mi * 16 + h * 8;
                const int c = col0 + ecol + ni * 8;
                const size_t o = (size_t)r * HH + c;
                float2 hv = *reinterpret_cast<const float2*>(addv + o);
                float2 v;
                v.x = acc[mi][ni][h * 2 + 0] + hv.x;
                v.y = acc[mi][ni][h * 2 + 1] + hv.y;
                *reinterpret_cast<float2*>(out + o) = v;
            }
}

// ================= split / transpose prep =================
__global__ void __launch_bounds__(256)
split_acts(const float* __restrict__ hidden, const float* __restrict__ sx,
           const float* __restrict__ tmk, const float* __restrict__ tmv,
           const float* __restrict__ tmr)
{
    const int idx = blockIdx.x * 256 + threadIdx.x;  // float4 index
    const int h4 = idx & (HH / 4 - 1);
    float4 hv = reinterpret_cast<const float4*>(hidden)[idx];
    float4 pv = (idx >= HH / 4) ? reinterpret_cast<const float4*>(hidden)[idx - HH / 4]
                                : reinterpret_cast<const float4*>(sx)[h4];
    const float* tms[3] = {tmk, tmv, tmr};
#pragma unroll
    for (int p = 0; p < 3; ++p) {
        float4 mv = reinterpret_cast<const float4*>(tms[p])[h4];
        union { __half b[4]; uint2 u; } Hh;
        Hh.b[0] = __float2half_rn(fmaf(hv.x - pv.x, mv.x, pv.x));
        Hh.b[1] = __float2half_rn(fmaf(hv.y - pv.y, mv.y, pv.y));
        Hh.b[2] = __float2half_rn(fmaf(hv.z - pv.z, mv.z, pv.z));
        Hh.b[3] = __float2half_rn(fmaf(hv.w - pv.w, mv.w, pv.w));
        *reinterpret_cast<uint2*>(&g_ax[p][(size_t)idx * 4]) = Hh.u;
    }
}

// W[K,N] -> W^T[N,K] fp16
__global__ void __launch_bounds__(256)
wtrans4(const float* __restrict__ W0, const float* __restrict__ W1,
        const float* __restrict__ W2, const float* __restrict__ W3)
{
    __shared__ float ts[32][33];
    const int z = blockIdx.z;
    const float* W = (z == 0) ? W0 : (z == 1) ? W1 : (z == 2) ? W2 : W3;
    __half* T = &g_wt[z][0];
    const int n0 = blockIdx.x * 32, k0 = blockIdx.y * 32;
    const int tx = threadIdx.x, ty = threadIdx.y;  // 32 x 8
#pragma unroll
    for (int i = 0; i < 4; ++i)
        ts[ty + i * 8][tx] = W[(size_t)(k0 + ty + i * 8) * HH + n0 + tx];
    __syncthreads();
#pragma unroll
    for (int i = 0; i < 4; ++i) {
        const size_t o = (size_t)(n0 + ty + i * 8) * HH + k0 + tx;
        T[o] = __float2half_rn(ts[tx][ty + i * 8]);
    }
}

// ================= WKV chunked scan (R14 structure) =================
__global__ void scan_phaseA(const float* __restrict__ td)
{
    int h2 = blockIdx.x * blockDim.x + threadIdx.x;
    int h = h2 * 2;
    int c = blockIdx.y;
    float w0 = -expf(td[h]), w1 = -expf(td[h + 1]);
    float a0 = 0.f, b0 = 0.f, p0 = -1e30f;
    float a1 = 0.f, b1 = 0.f, p1 = -1e30f;
    int t0 = c * CLEN;
#pragma unroll 4
    for (int t = t0; t < t0 + CLEN; ++t) {
        size_t idx = (size_t)t * HH + h;
        float2 kk = __half22float2(*reinterpret_cast<const __half2*>(&g_kh[idx]));
        float2 vv = __half22float2(*reinterpret_cast<const __half2*>(&g_vh[idx]));
        {
            float ww = w0 + p0, d = ww - kk.x;
            float e = __expf(-fabsf(d));
            float e1 = (d >= 0.f) ? 1.f : e, e2 = (d >= 0.f) ? e : 1.f;
            a0 = e1 * a0 + e2 * vv.x; b0 = e1 * b0 + e2; p0 = fmaxf(ww, kk.x);
        }
        {
            float ww = w1 + p1, d = ww - kk.y;
            float e = __expf(-fabsf(d));
            float e1 = (d >= 0.f) ? 1.f : e, e2 = (d >= 0.f) ? e : 1.f;
            a1 = e1 * a1 + e2 * vv.y; b1 = e1 * b1 + e2; p1 = fmaxf(ww, kk.y);
        }
    }
    *reinterpret_cast<float2*>(&g_Sa[c * HH + h]) = make_float2(a0, a1);
    *reinterpret_cast<float2*>(&g_Sb[c * HH + h]) = make_float2(b0, b1);
    *reinterpret_cast<float2*>(&g_Sm[c * HH + h]) = make_float2(p0, p1);
}

__global__ void scan_phaseB(const float* __restrict__ td,
                            const float* __restrict__ aa0, const float* __restrict__ bb0,
                            const float* __restrict__ pp0, const float* __restrict__ hidden,
                            float* __restrict__ out)
{
    int h = blockIdx.x * blockDim.x + threadIdx.x;
    float w = -expf(td[h]);
    float wL = w * (float)CLEN;
    float a = aa0[h], b = bb0[h], p = pp0[h];
    float sa = g_Sa[h], sb = g_Sb[h], sm = g_Sm[h];
    for (int c = 0; c < NCHUNK; ++c) {
        float nsa, nsb, nsm;
        if (c + 1 < NCHUNK) {
            nsa = g_Sa[(c + 1) * HH + h];
            nsb = g_Sb[(c + 1) * HH + h];
            nsm = g_Sm[(c + 1) * HH + h];
        }
        g_Pa[c * HH + h] = a;
        g_Pb[c * HH + h] = b;
        g_Pp[c * HH + h] = p;
        float pd = p + wL;
        float d = pd - sm;
        float e = __expf(-fabsf(d));
        float e1 = (d >= 0.f) ? 1.f : e, e2 = (d >= 0.f) ? e : 1.f;
        a = e1 * a + e2 * sa;
        b = e1 * b + e2 * sb;
        p = fmaxf(pd, sm);
        sa = nsa; sb = nsb; sm = nsm;
    }
    out[TT * HH + h] = hidden[(TT - 1) * HH + h];
    out[TT * HH + HH + h] = a;
    out[TT * HH + 2 * HH + h] = b;
    out[TT * HH + 3 * HH + h] = p;
}

__global__ void scan_phaseC(const float* __restrict__ td, const float* __restrict__ tf)
{
    int h2 = blockIdx.x * blockDim.x + threadIdx.x;
    int h = h2 * 2;
    int c = blockIdx.y;
    float w0 = -expf(td[h]), w1 = -expf(td[h + 1]);
    float u0 = tf[h], u1 = tf[h + 1];
    float2 Pa = *reinterpret_cast<const float2*>(&g_Pa[c * HH + h]);
    float2 Pb = *reinterpret_cast<const float2*>(&g_Pb[c * HH + h]);
    float2 Pp = *reinterpret_cast<const float2*>(&g_Pp[c * HH + h]);
    float a0 = Pa.x, b0 = Pb.x, p0 = Pp.x;
    float a1 = Pa.y, b1 = Pb.y, p1 = Pp.y;
    int t0 = c * CLEN;
#pragma unroll 4
    for (int t = t0; t < t0 + CLEN; ++t) {
        size_t idx = (size_t)t * HH + h;
        float2 kk = __half22float2(*reinterpret_cast<const __half2*>(&g_kh[idx]));
        float2 vv = __half22float2(*reinterpret_cast<const __half2*>(&g_vh[idx]));
        float2 rr = __half22float2(*reinterpret_cast<const __half2*>(&g_rh[idx]));
        float rw0, rw1;
        {
            float ww = u0 + kk.x, d1 = p0 - ww;
            float e = __expf(-fabsf(d1));
            float e1 = (d1 >= 0.f) ? 1.f : e, e2 = (d1 >= 0.f) ? e : 1.f;
            float num = e1 * a0 + e2 * vv.x;
            float den = e1 * b0 + e2;
            float sr = 1.f + __expf(-rr.x);
            rw0 = num * __frcp_rn(den * sr);
            float ww2 = w0 + p0, d2 = ww2 - kk.x;
            float f = __expf(-fabsf(d2));
            float f1 = (d2 >= 0.f) ? 1.f : f, f2 = (d2 >= 0.f) ? f : 1.f;
            a0 = f1 * a0 + f2 * vv.x; b0 = f1 * b0 + f2; p0 = fmaxf(ww2, kk.x);
        }
        {
            float ww = u1 + kk.y, d1 = p1 - ww;
            float e = __expf(-fabsf(d1));
            float e1 = (d1 >= 0.f) ? 1.f : e, e2 = (d1 >= 0.f) ? e : 1.f;
            float num = e1 * a1 + e2 * vv.y;
            float den = e1 * b1 + e2;
            float sr = 1.f + __expf(-rr.y);
            rw1 = num * __frcp_rn(den * sr);
            float ww2 = w1 + p1, d2 = ww2 - kk.y;
            float f = __expf(-fabsf(d2));
            float f1 = (d2 >= 0.f) ? 1.f : f, f2 = (d2 >= 0.f) ? f : 1.f;
            a1 = f1 * a1 + f2 * vv.y; b1 = f1 * b1 + f2; p1 = fmaxf(ww2, kk.y);
        }
        *reinterpret_cast<__half2*>(&g_rw[idx]) = __floats2half2_rn(rw0, rw1);
    }
}

extern "C" void kernel_launch(void* const* d_in, const int* in_sizes, int n_in,
                              void* d_out, int out_size)
{
    const float* hidden = (const float*)d_in[0];
    const float* sx     = (const float*)d_in[1];
    const float* aa     = (const float*)d_in[2];
    const float* bb     = (const float*)d_in[3];
    const float* pp     = (const float*)d_in[4];
    const float* td     = (const float*)d_in[5];
    const float* tf     = (const float*)d_in[6];
    const float* tmk    = (const float*)d_in[7];
    const float* tmv    = (const float*)d_in[8];
    const float* tmr    = (const float*)d_in[9];
    const float* Wk     = (const float*)d_in[10];
    const float* Wv     = (const float*)d_in[11];
    const float* Wr     = (const float*)d_in[12];
    const float* Wo     = (const float*)d_in[13];
    float* out = (float*)d_out;

    cudaFuncSetAttribute(mmagemm_kvr, cudaFuncAttributeMaxDynamicSharedMemorySize, GSMEM);
    cudaFuncSetAttribute(mmagemm_out, cudaFuncAttributeMaxDynamicSharedMemorySize, GSMEM);

    // side stream + events for captured fork/join (host-side objects; created
    // per call — kernel_launch runs only a couple of times, no device memory)
    cudaStream_t s2;
    cudaStreamCreateWithFlags(&s2, cudaStreamNonBlocking);
    cudaEvent_t e0, e1, e2, e3;
    cudaEventCreateWithFlags(&e0, cudaEventDisableTiming);
    cudaEventCreateWithFlags(&e1, cudaEventDisableTiming);
    cudaEventCreateWithFlags(&e2, cudaEventDisableTiming);
    cudaEventCreateWithFlags(&e3, cudaEventDisableTiming);

    // fork 1: wtrans on s2 overlaps split_acts on main
    cudaEventRecord(e0, 0);
    cudaStreamWaitEvent(s2, e0, 0);
    dim3 wgrid(HH / 32, HH / 32, 4), wblk(32, 8);
    wtrans4<<<wgrid, wblk, 0, s2>>>(Wk, Wv, Wr, Wo);
    cudaEventRecord(e1, s2);

    split_acts<<<(TT * HH / 4) / 256, 256>>>(hidden, sx, tmk, tmv, tmr);
    cudaStreamWaitEvent(0, e1, 0);

    // kv GEMM (z = 0,1)
    dim3 gkv(HH / BN, TT / BM, 2);
    mmagemm_kvr<<<gkv, 256, GSMEM>>>(0);

    // fork 2: phaseA+phaseB on s2 overlap r-GEMM on main
    cudaEventRecord(e2, 0);
    cudaStreamWaitEvent(s2, e2, 0);
    dim3 sgrid(HH / 2 / 256, NCHUNK);
    scan_phaseA<<<sgrid, 256, 0, s2>>>(td);
    scan_phaseB<<<HH / 256, 256, 0, s2>>>(td, aa, bb, pp, hidden, out);
    cudaEventRecord(e3, s2);

    dim3 gr(HH / BN, TT / BM, 1);
    mmagemm_kvr<<<gr, 256, GSMEM>>>(2);
    cudaStreamWaitEvent(0, e3, 0);

    scan_phaseC<<<sgrid, 256>>>(td, tf);

    dim3 gg(HH / BN, TT / BM);
    mmagemm_out<<<gg, 256, GSMEM>>>(hidden, out);
}